// round 11
// baseline (speedup 1.0000x reference)
#include <cuda_runtime.h>
#include <cuda_bf16.h>
#include <cstdint>
#include <math.h>

// Problem constants
constexpr int Bb = 4;
constexpr int T  = 2048;
constexpr int C  = 1024;
constexpr int H  = 16;
constexpr int D  = 64;
constexpr int M  = Bb * T;   // 8192

// ---------------------------------------------------------------------------
// Device scratch (allocation-free rule)
// ---------------------------------------------------------------------------
__device__ __nv_bfloat16 g_qh[(size_t)Bb * H * T * D];
__device__ __nv_bfloat16 g_ql[(size_t)Bb * H * T * D];
__device__ __nv_bfloat16 g_kh[(size_t)Bb * H * T * D];
__device__ __nv_bfloat16 g_kl[(size_t)Bb * H * T * D];
__device__ __nv_bfloat16 g_vh[(size_t)Bb * H * T * D];
__device__ __nv_bfloat16 g_vl[(size_t)Bb * H * T * D];
__device__ __nv_bfloat16 g_xh[(size_t)M * C];
__device__ __nv_bfloat16 g_xl[(size_t)M * C];
__device__ __nv_bfloat16 g_yh[(size_t)M * C];
__device__ __nv_bfloat16 g_yl[(size_t)M * C];
// transposed weights [N][K], order: q, k, v, p
__device__ __nv_bfloat16 g_wh[(size_t)4 * C * C];
__device__ __nv_bfloat16 g_wl[(size_t)4 * C * C];

// ---------------------------------------------------------------------------
// Baseline-PTX helpers (no sm_103a-only features)
// ---------------------------------------------------------------------------
__device__ __forceinline__ uint32_t smem_to_u32(const void* p) {
    uint32_t a;
    asm("{ .reg .u64 t; cvta.to.shared.u64 t, %1; cvt.u32.u64 %0, t; }"
        : "=r"(a) : "l"(p));
    return a;
}
__device__ __forceinline__ void cp_async16(uint32_t dst, const void* src) {
    asm volatile("cp.async.cg.shared.global [%0], [%1], 16;"
                 :: "r"(dst), "l"(src) : "memory");
}
#define CP_COMMIT() asm volatile("cp.async.commit_group;" ::: "memory")
#define CP_WAIT(n)  asm volatile("cp.async.wait_group %0;" :: "n"(n) : "memory")

__device__ __forceinline__ void ldsm_x4(uint32_t& r0, uint32_t& r1,
                                        uint32_t& r2, uint32_t& r3, uint32_t addr) {
    asm volatile("ldmatrix.sync.aligned.m8n8.x4.shared.b16 {%0,%1,%2,%3}, [%4];"
                 : "=r"(r0), "=r"(r1), "=r"(r2), "=r"(r3) : "r"(addr));
}
__device__ __forceinline__ void ldsm_x4_t(uint32_t& r0, uint32_t& r1,
                                          uint32_t& r2, uint32_t& r3, uint32_t addr) {
    asm volatile("ldmatrix.sync.aligned.m8n8.x4.trans.shared.b16 {%0,%1,%2,%3}, [%4];"
                 : "=r"(r0), "=r"(r1), "=r"(r2), "=r"(r3) : "r"(addr));
}
__device__ __forceinline__ void mma_bf16(float* d, const uint32_t* a, const uint32_t* b) {
    asm volatile(
        "mma.sync.aligned.m16n8k16.row.col.f32.bf16.bf16.f32 "
        "{%0,%1,%2,%3}, {%4,%5,%6,%7}, {%8,%9}, {%0,%1,%2,%3};"
        : "+f"(d[0]), "+f"(d[1]), "+f"(d[2]), "+f"(d[3])
        : "r"(a[0]), "r"(a[1]), "r"(a[2]), "r"(a[3]), "r"(b[0]), "r"(b[1]));
}
__device__ __forceinline__ void split_pack(uint32_t& hi, uint32_t& lo, float a, float b) {
    __nv_bfloat162 h2 = __floats2bfloat162_rn(a, b);
    float2 hf = __bfloat1622float2(h2);
    __nv_bfloat162 l2 = __floats2bfloat162_rn(a - hf.x, b - hf.y);
    hi = *reinterpret_cast<uint32_t*>(&h2);
    lo = *reinterpret_cast<uint32_t*>(&l2);
}

// ---------------------------------------------------------------------------
// Conversion kernels
// ---------------------------------------------------------------------------
__global__ void __launch_bounds__(256)
convert_x_kernel(const float* __restrict__ x)
{
    size_t i4 = ((size_t)blockIdx.x * 256 + threadIdx.x) * 4;
    float4 v = *(const float4*)(x + i4);
    float vv[4] = {v.x, v.y, v.z, v.w};
    #pragma unroll
    for (int j = 0; j < 4; j++) {
        __nv_bfloat16 h = __float2bfloat16(vv[j]);
        g_xh[i4 + j] = h;
        g_xl[i4 + j] = __float2bfloat16(vv[j] - __bfloat162float(h));
    }
}

__global__ void __launch_bounds__(256)
convert_w_kernel(const float* __restrict__ Wq, const float* __restrict__ Wk,
                 const float* __restrict__ Wv, const float* __restrict__ Wp)
{
    __shared__ float tile[32][33];
    const int z = blockIdx.z;
    const float* W = (z == 0) ? Wq : (z == 1) ? Wk : (z == 2) ? Wv : Wp;
    const int n0 = blockIdx.x * 32, k0 = blockIdx.y * 32;
    const int tx = threadIdx.x & 31, ty = threadIdx.x >> 5;

    #pragma unroll
    for (int i = 0; i < 4; i++)
        tile[ty + i * 8][tx] = W[(size_t)(k0 + ty + i * 8) * C + n0 + tx];
    __syncthreads();

    __nv_bfloat16* wh = g_wh + (size_t)z * C * C;
    __nv_bfloat16* wl = g_wl + (size_t)z * C * C;
    #pragma unroll
    for (int i = 0; i < 4; i++) {
        const int n = n0 + ty + i * 8;
        const int k = k0 + tx;
        float v = tile[tx][ty + i * 8];
        __nv_bfloat16 h = __float2bfloat16(v);
        wh[(size_t)n * C + k] = h;
        wl[(size_t)n * C + k] = __float2bfloat16(v - __bfloat162float(h));
    }
}

// ---------------------------------------------------------------------------
// mma.sync split-bf16 GEMM, 256x128 CTA tile, 512 threads (4m x 4n warps).
// MODE 0: qkv -> split bf16 [B,H,T,D] (q pre-scaled by log2e/sqrt(D)).
// MODE 1: proj -> fp32 d_out.
// ---------------------------------------------------------------------------
constexpr int APITCHB  = 80;
constexpr int AMAT_B   = 256 * APITCHB;                 // 20480
constexpr int BMAT_B   = 128 * APITCHB;                 // 10240
constexpr int STAGE_B2 = 2 * AMAT_B + 2 * BMAT_B;       // 61440
constexpr int GE_SMEM  = 2 * STAGE_B2;                  // 122880

template<int MODE>
__global__ void __launch_bounds__(512, 1)
gemm_mma_kernel(const float* __restrict__ bias0, const float* __restrict__ bias1,
                const float* __restrict__ bias2, float* __restrict__ outp)
{
    extern __shared__ char smem[];
    const uint32_t sb = smem_to_u32(smem);
    const int tid  = threadIdx.x;
    const int wid  = tid >> 5;
    const int lane = tid & 31;
    const int warp_m = (wid & 3) * 64;     // 0,64,128,192
    const int warp_n = (wid >> 2) * 32;    // 0,32,64,96

    const int z = (MODE == 0) ? blockIdx.z : 3;
    const __nv_bfloat16* Ah = (MODE == 0) ? g_xh : g_yh;
    const __nv_bfloat16* Al = (MODE == 0) ? g_xl : g_yl;
    const __nv_bfloat16* Bh = g_wh + (size_t)z * C * C;
    const __nv_bfloat16* Bl = g_wl + (size_t)z * C * C;
    const float* bias = (MODE == 1) ? bias0 : (z == 0) ? bias0 : (z == 1) ? bias1 : bias2;
    __nv_bfloat16* outh = (z == 0) ? g_qh : (z == 1) ? g_kh : g_vh;
    __nv_bfloat16* outl = (z == 0) ? g_ql : (z == 1) ? g_kl : g_vl;
    // q pre-scaled by (1/sqrt(D)) * log2(e) so softmax can run in base 2
    const float oscale = (MODE == 0 && z == 0) ? 0.1803368801111244f : 1.0f;

    const int brow = blockIdx.y * 256;
    const int bcol = blockIdx.x * 128;

    // A: 1024 16B-chunks per matrix / 512 threads = 2 slots; B: 512 / 512 = 1
    uint32_t soffA[2];
    size_t goffA[2];
    #pragma unroll
    for (int i = 0; i < 2; i++) {
        const int id = tid + i * 512;
        const int row = id >> 2, cc = id & 3;
        soffA[i] = (uint32_t)(row * APITCHB + cc * 16);
        goffA[i] = (size_t)(brow + row) * C + cc * 8;
    }
    const int brB = tid >> 2, ccB = tid & 3;
    const uint32_t soffB = (uint32_t)(brB * APITCHB + ccB * 16);
    const size_t goffB = (size_t)(bcol + brB) * C + ccB * 8;

    auto issue = [&](int s) {
        const int k0 = s * 32;
        const uint32_t base = sb + (uint32_t)(s & 1) * STAGE_B2;
        #pragma unroll
        for (int i = 0; i < 2; i++) {
            cp_async16(base +          soffA[i], Ah + goffA[i] + k0);
            cp_async16(base + AMAT_B + soffA[i], Al + goffA[i] + k0);
        }
        cp_async16(base + 2 * AMAT_B +          soffB, Bh + goffB + k0);
        cp_async16(base + 2 * AMAT_B + BMAT_B + soffB, Bl + goffB + k0);
        CP_COMMIT();
    };

    float acc[4][4][4] = {};

    const int a_row  = warp_m + (lane & 15);
    const uint32_t a_half = (uint32_t)(lane >> 4) * 16;
    const int tt = lane >> 3;
    const int b_row  = warp_n + (tt >> 1) * 8 + (lane & 7);
    const uint32_t b_half = (uint32_t)(tt & 1) * 16;

    constexpr int NS = C / 32;
    issue(0);

    for (int s = 0; s < NS; s++) {
        if (s + 1 < NS) { issue(s + 1); CP_WAIT(1); }
        else            { CP_WAIT(0); }
        __syncthreads();

        const uint32_t base = sb + (uint32_t)(s & 1) * STAGE_B2;
        #pragma unroll
        for (int ks = 0; ks < 2; ks++) {
            const uint32_t kb = (uint32_t)ks * 32;

            uint32_t ah[4][4], al[4][4];
            #pragma unroll
            for (int mt = 0; mt < 4; mt++) {
                const uint32_t ao = (uint32_t)((a_row + mt * 16) * APITCHB) + kb + a_half;
                ldsm_x4(ah[mt][0], ah[mt][1], ah[mt][2], ah[mt][3], base + ao);
                ldsm_x4(al[mt][0], al[mt][1], al[mt][2], al[mt][3], base + AMAT_B + ao);
            }
            uint32_t bh[4][2], bl[4][2];
            #pragma unroll
            for (int np = 0; np < 2; np++) {
                const uint32_t bo = (uint32_t)((b_row + np * 16) * APITCHB) + kb + b_half;
                uint32_t r0, r1, r2, r3;
                ldsm_x4(r0, r1, r2, r3, base + 2 * AMAT_B + bo);
                bh[np * 2][0] = r0; bh[np * 2][1] = r1;
                bh[np * 2 + 1][0] = r2; bh[np * 2 + 1][1] = r3;
                ldsm_x4(r0, r1, r2, r3, base + 2 * AMAT_B + BMAT_B + bo);
                bl[np * 2][0] = r0; bl[np * 2][1] = r1;
                bl[np * 2 + 1][0] = r2; bl[np * 2 + 1][1] = r3;
            }
            #pragma unroll
            for (int mt = 0; mt < 4; mt++)
                #pragma unroll
                for (int nt = 0; nt < 4; nt++) {
                    mma_bf16(acc[mt][nt], ah[mt], bh[nt]);
                    mma_bf16(acc[mt][nt], ah[mt], bl[nt]);
                    mma_bf16(acc[mt][nt], al[mt], bh[nt]);
                }
        }
        __syncthreads();
    }

    #pragma unroll
    for (int nt = 0; nt < 4; nt++) {
        const int n = bcol + warp_n + nt * 8 + (lane & 3) * 2;
        const float bn0 = __ldg(bias + n);
        const float bn1 = __ldg(bias + n + 1);
        #pragma unroll
        for (int mt = 0; mt < 4; mt++) {
            #pragma unroll
            for (int half = 0; half < 2; half++) {
                const int m = brow + warp_m + mt * 16 + (lane >> 2) + half * 8;
                const float v0 = (acc[mt][nt][half * 2 + 0] + bn0) * oscale;
                const float v1 = (acc[mt][nt][half * 2 + 1] + bn1) * oscale;
                if (MODE == 1) {
                    *(float2*)&outp[(size_t)m * C + n] = make_float2(v0, v1);
                } else {
                    const int bi = m >> 11, t = m & (T - 1);
                    const int hh = n >> 6, d = n & (D - 1);
                    const size_t idx = (((size_t)(bi * H + hh)) * T + t) * D + d;
                    uint32_t hi, lo;
                    split_pack(hi, lo, v0, v1);
                    *reinterpret_cast<uint32_t*>(&outh[idx]) = hi;
                    *reinterpret_cast<uint32_t*>(&outl[idx]) = lo;
                }
            }
        }
    }
}

// ---------------------------------------------------------------------------
// Tensor-core flash attention (causal), split-bf16 3-term MMA, base-2 softmax.
// CTA: 128 q-rows, 8 warps x 16 rows. K-tiles of 64 keys, double-buffered.
// ---------------------------------------------------------------------------
constexpr int QPITCH  = 144;
constexpr int QMAT    = 128 * QPITCH;     // 18432
constexpr int KVMAT   = 64 * QPITCH;      // 9216
constexpr int KVSTAGE = 4 * KVMAT;        // 36864
constexpr int FA_SMEM = 2 * QMAT + 2 * KVSTAGE;  // 110592

__global__ void __launch_bounds__(256, 2)
flash_mma_kernel()
{
    extern __shared__ char smem[];
    const uint32_t sb = smem_to_u32(smem);
    const int tid  = threadIdx.x;
    const int wid  = tid >> 5;
    const int lane = tid & 31;
    const int gq   = lane >> 2;
    const int cq   = lane & 3;

    const int bh = blockIdx.y;
    const int qi = gridDim.x - 1 - blockIdx.x;     // heavy CTAs first
    const int qt = qi * 128;
    const size_t hoff = (size_t)bh * T * D;

    const __nv_bfloat16* kv_src[4] = {g_kh + hoff, g_kl + hoff, g_vh + hoff, g_vl + hoff};

    // issue Q (group), then KV stage 0
    {
        #pragma unroll
        for (int i = 0; i < 8; i++) {
            const int id = tid + i * 256;
            const int mat = id >> 10;
            const int cid = id & 1023;
            const int row = cid >> 3, cc = cid & 7;
            const __nv_bfloat16* src =
                (mat ? g_ql : g_qh) + hoff + (size_t)(qt + row) * D + cc * 8;
            cp_async16(sb + (uint32_t)(mat * QMAT + row * QPITCH + cc * 16), src);
        }
        CP_COMMIT();
    }
    auto issueKV = [&](int s_) {
        const int kt_ = s_ * 64;
        const uint32_t base = sb + 2 * QMAT + (uint32_t)(s_ & 1) * KVSTAGE;
        #pragma unroll
        for (int i = 0; i < 8; i++) {
            const int id = tid + i * 256;
            const int mat = id >> 9;
            const int cid = id & 511;
            const int row = cid >> 3, cc = cid & 7;
            cp_async16(base + (uint32_t)(mat * KVMAT + row * QPITCH + cc * 16),
                       kv_src[mat] + (size_t)(kt_ + row) * D + cc * 8);
        }
        CP_COMMIT();
    };
    issueKV(0);
    CP_WAIT(1);          // Q group done
    __syncthreads();

    // Q hi fragments resident; lo fragments reloaded per tile (register lean)
    const int qrow  = wid * 16 + (lane & 7) + ((lane >> 3) & 1) * 8;
    const int qcolb = (lane >> 4) * 8;
    uint32_t qfh[4][4];
    #pragma unroll
    for (int t = 0; t < 4; t++) {
        const uint32_t addr = sb + (uint32_t)(qrow * QPITCH + (t * 16 + qcolb) * 2);
        ldsm_x4(qfh[t][0], qfh[t][1], qfh[t][2], qfh[t][3], addr);
    }

    float oacc[8][4] = {};
    float m0 = -1e30f, m1 = -1e30f, l0 = 0.f, l1 = 0.f;
    const int qw0 = qt + wid * 16;
    const int ns = (qt >> 6) + 2;

    for (int s = 0; s < ns; s++) {
        if (s + 1 < ns) { issueKV(s + 1); CP_WAIT(1); }
        else            { CP_WAIT(0); }
        __syncthreads();

        const int kt = s * 64;
        if (kt <= qw0 + 15) {
            const uint32_t kvb = sb + 2 * QMAT + (uint32_t)(s & 1) * KVSTAGE;

            // S = Q K^T (split 3-term), logits already in log2 domain
            float sacc[8][4] = {};
            {
                const int kro = (lane & 7) + (lane >> 4) * 8;
                const int kco = ((lane >> 3) & 1) * 8;
                #pragma unroll
                for (int t = 0; t < 4; t++) {
                    uint32_t qlt[4];
                    const uint32_t qaddr = sb + QMAT +
                        (uint32_t)(qrow * QPITCH + (t * 16 + qcolb) * 2);
                    ldsm_x4(qlt[0], qlt[1], qlt[2], qlt[3], qaddr);
                    #pragma unroll
                    for (int jp = 0; jp < 4; jp++) {
                        uint32_t kh_[4], kl_[4];
                        const uint32_t addr = kvb +
                            (uint32_t)((jp * 16 + kro) * QPITCH + (t * 16 + kco) * 2);
                        ldsm_x4(kh_[0], kh_[1], kh_[2], kh_[3], addr);
                        ldsm_x4(kl_[0], kl_[1], kl_[2], kl_[3], addr + KVMAT);
                        #pragma unroll
                        for (int half = 0; half < 2; half++) {
                            const int n = jp * 2 + half;
                            mma_bf16(sacc[n], qfh[t], &kh_[half * 2]);
                            mma_bf16(sacc[n], qfh[t], &kl_[half * 2]);
                            mma_bf16(sacc[n], qlt,    &kh_[half * 2]);
                        }
                    }
                }
            }

            // causal mask (diagonal tiles only)
            if (kt + 63 > qw0) {
                const int q0 = qw0 + gq, q1 = q0 + 8;
                #pragma unroll
                for (int n = 0; n < 8; n++) {
                    const int key = kt + n * 8 + cq * 2;
                    if (key     > q0) sacc[n][0] = -1e30f;
                    if (key + 1 > q0) sacc[n][1] = -1e30f;
                    if (key     > q1) sacc[n][2] = -1e30f;
                    if (key + 1 > q1) sacc[n][3] = -1e30f;
                }
            }

            // online softmax (base 2)
            float tm0 = -1e30f, tm1 = -1e30f;
            #pragma unroll
            for (int n = 0; n < 8; n++) {
                tm0 = fmaxf(tm0, fmaxf(sacc[n][0], sacc[n][1]));
                tm1 = fmaxf(tm1, fmaxf(sacc[n][2], sacc[n][3]));
            }
            tm0 = fmaxf(tm0, __shfl_xor_sync(0xffffffffu, tm0, 1));
            tm0 = fmaxf(tm0, __shfl_xor_sync(0xffffffffu, tm0, 2));
            tm1 = fmaxf(tm1, __shfl_xor_sync(0xffffffffu, tm1, 1));
            tm1 = fmaxf(tm1, __shfl_xor_sync(0xffffffffu, tm1, 2));
            const float nm0 = fmaxf(m0, tm0), nm1 = fmaxf(m1, tm1);
            const float al0 = exp2f(m0 - nm0), al1 = exp2f(m1 - nm1);
            m0 = nm0; m1 = nm1;
            float s0 = 0.f, s1 = 0.f;
            #pragma unroll
            for (int n = 0; n < 8; n++) {
                sacc[n][0] = exp2f(sacc[n][0] - nm0); s0 += sacc[n][0];
                sacc[n][1] = exp2f(sacc[n][1] - nm0); s0 += sacc[n][1];
                sacc[n][2] = exp2f(sacc[n][2] - nm1); s1 += sacc[n][2];
                sacc[n][3] = exp2f(sacc[n][3] - nm1); s1 += sacc[n][3];
            }
            s0 += __shfl_xor_sync(0xffffffffu, s0, 1);
            s0 += __shfl_xor_sync(0xffffffffu, s0, 2);
            s1 += __shfl_xor_sync(0xffffffffu, s1, 1);
            s1 += __shfl_xor_sync(0xffffffffu, s1, 2);
            l0 = l0 * al0 + s0;
            l1 = l1 * al1 + s1;
            #pragma unroll
            for (int j = 0; j < 8; j++) {
                oacc[j][0] *= al0; oacc[j][1] *= al0;
                oacc[j][2] *= al1; oacc[j][3] *= al1;
            }

            // O += P V (split 3-term); P packed from accumulators
            {
                const int vro = (lane & 7) + ((lane >> 3) & 1) * 8;
                const int vco = (lane >> 4) * 8;
                #pragma unroll
                for (int t = 0; t < 4; t++) {
                    uint32_t pah[4], pal[4];
                    split_pack(pah[0], pal[0], sacc[2 * t][0],     sacc[2 * t][1]);
                    split_pack(pah[1], pal[1], sacc[2 * t][2],     sacc[2 * t][3]);
                    split_pack(pah[2], pal[2], sacc[2 * t + 1][0], sacc[2 * t + 1][1]);
                    split_pack(pah[3], pal[3], sacc[2 * t + 1][2], sacc[2 * t + 1][3]);
                    #pragma unroll
                    for (int jp = 0; jp < 4; jp++) {
                        uint32_t vh_[4], vl_[4];
                        const uint32_t addr = kvb + 2 * KVMAT +
                            (uint32_t)((t * 16 + vro) * QPITCH + (jp * 16 + vco) * 2);
                        ldsm_x4_t(vh_[0], vh_[1], vh_[2], vh_[3], addr);
                        ldsm_x4_t(vl_[0], vl_[1], vl_[2], vl_[3], addr + KVMAT);
                        #pragma unroll
                        for (int half = 0; half < 2; half++) {
                            const int j = jp * 2 + half;
                            mma_bf16(oacc[j], pah, &vh_[half * 2]);
                            mma_bf16(oacc[j], pah, &vl_[half * 2]);
                            mma_bf16(oacc[j], pal, &vh_[half * 2]);
                        }
                    }
                }
            }
        }
        __syncthreads();
    }

    // epilogue: y = O / l, split-bf16 into g_yh/g_yl at [b, t, h*D + d]
    const int b = bh >> 4, h = bh & (H - 1);
    const float i0 = 1.0f / l0, i1 = 1.0f / l1;
    const int r0a = qw0 + gq, r1a = r0a + 8;
    #pragma unroll
    for (int j = 0; j < 8; j++) {
        const int col = j * 8 + cq * 2;
        const size_t idx0 = ((size_t)(b * T + r0a)) * C + h * D + col;
        const size_t idx1 = ((size_t)(b * T + r1a)) * C + h * D + col;
        uint32_t hh, ll;
        split_pack(hh, ll, oacc[j][0] * i0, oacc[j][1] * i0);
        *reinterpret_cast<uint32_t*>(&g_yh[idx0]) = hh;
        *reinterpret_cast<uint32_t*>(&g_yl[idx0]) = ll;
        split_pack(hh, ll, oacc[j][2] * i1, oacc[j][3] * i1);
        *reinterpret_cast<uint32_t*>(&g_yh[idx1]) = hh;
        *reinterpret_cast<uint32_t*>(&g_yl[idx1]) = ll;
    }
}

// ---------------------------------------------------------------------------
// Launch
// ---------------------------------------------------------------------------
extern "C" void kernel_launch(void* const* d_in, const int* in_sizes, int n_in,
                              void* d_out, int out_size)
{
    const float* x  = (const float*)d_in[0];
    const float* Wk = (const float*)d_in[1];
    const float* bk = (const float*)d_in[2];
    const float* Wq = (const float*)d_in[3];
    const float* bq = (const float*)d_in[4];
    const float* Wv = (const float*)d_in[5];
    const float* bv = (const float*)d_in[6];
    const float* Wp = (const float*)d_in[7];
    const float* bp = (const float*)d_in[8];
    float* out = (float*)d_out;

    // 0) conversions
    convert_x_kernel<<<(M * C) / (256 * 4), 256>>>(x);
    convert_w_kernel<<<dim3(C / 32, C / 32, 4), 256>>>(Wq, Wk, Wv, Wp);

    // 1) QKV projections (mma.sync bf16 split, split-bf16 outputs)
    cudaFuncSetAttribute(gemm_mma_kernel<0>,
                         cudaFuncAttributeMaxDynamicSharedMemorySize, GE_SMEM);
    gemm_mma_kernel<0><<<dim3(C / 128, M / 256, 3), 512, GE_SMEM>>>(bq, bk, bv, nullptr);

    // 2) causal flash attention on tensor cores
    cudaFuncSetAttribute(flash_mma_kernel,
                         cudaFuncAttributeMaxDynamicSharedMemorySize, FA_SMEM);
    flash_mma_kernel<<<dim3(T / 128, Bb * H), 256, FA_SMEM>>>();

    // 3) output projection (mma.sync bf16 split)
    cudaFuncSetAttribute(gemm_mma_kernel<1>,
                         cudaFuncAttributeMaxDynamicSharedMemorySize, GE_SMEM);
    gemm_mma_kernel<1><<<dim3(C / 128, M / 256, 1), 512, GE_SMEM>>>(bp, nullptr, nullptr, out);
}

// round 14
// speedup vs baseline: 1.7163x; 1.7163x over previous
#include <cuda_runtime.h>
#include <cuda_bf16.h>
#include <cstdint>
#include <math.h>

// Problem constants
constexpr int Bb = 4;
constexpr int T  = 2048;
constexpr int C  = 1024;
constexpr int H  = 16;
constexpr int D  = 64;
constexpr int M  = Bb * T;   // 8192

// ---------------------------------------------------------------------------
// Device scratch (allocation-free rule)
// ---------------------------------------------------------------------------
__device__ __nv_bfloat16 g_qh[(size_t)Bb * H * T * D];
__device__ __nv_bfloat16 g_ql[(size_t)Bb * H * T * D];
__device__ __nv_bfloat16 g_kh[(size_t)Bb * H * T * D];
__device__ __nv_bfloat16 g_kl[(size_t)Bb * H * T * D];
__device__ __nv_bfloat16 g_vh[(size_t)Bb * H * T * D];
__device__ __nv_bfloat16 g_vl[(size_t)Bb * H * T * D];
__device__ __nv_bfloat16 g_xh[(size_t)M * C];
__device__ __nv_bfloat16 g_xl[(size_t)M * C];
__device__ __nv_bfloat16 g_yh[(size_t)M * C];
__device__ __nv_bfloat16 g_yl[(size_t)M * C];
// transposed weights [N][K], order: q, k, v, p
__device__ __nv_bfloat16 g_wh[(size_t)4 * C * C];
__device__ __nv_bfloat16 g_wl[(size_t)4 * C * C];

// ---------------------------------------------------------------------------
// Baseline-PTX helpers (no sm_103a-only features)
// ---------------------------------------------------------------------------
__device__ __forceinline__ uint32_t smem_to_u32(const void* p) {
    uint32_t a;
    asm("{ .reg .u64 t; cvta.to.shared.u64 t, %1; cvt.u32.u64 %0, t; }"
        : "=r"(a) : "l"(p));
    return a;
}
__device__ __forceinline__ void cp_async16(uint32_t dst, const void* src) {
    asm volatile("cp.async.cg.shared.global [%0], [%1], 16;"
                 :: "r"(dst), "l"(src) : "memory");
}
#define CP_COMMIT() asm volatile("cp.async.commit_group;" ::: "memory")
#define CP_WAIT(n)  asm volatile("cp.async.wait_group %0;" :: "n"(n) : "memory")

__device__ __forceinline__ void ldsm_x4(uint32_t& r0, uint32_t& r1,
                                        uint32_t& r2, uint32_t& r3, uint32_t addr) {
    asm volatile("ldmatrix.sync.aligned.m8n8.x4.shared.b16 {%0,%1,%2,%3}, [%4];"
                 : "=r"(r0), "=r"(r1), "=r"(r2), "=r"(r3) : "r"(addr));
}
__device__ __forceinline__ void ldsm_x4_t(uint32_t& r0, uint32_t& r1,
                                          uint32_t& r2, uint32_t& r3, uint32_t addr) {
    asm volatile("ldmatrix.sync.aligned.m8n8.x4.trans.shared.b16 {%0,%1,%2,%3}, [%4];"
                 : "=r"(r0), "=r"(r1), "=r"(r2), "=r"(r3) : "r"(addr));
}
__device__ __forceinline__ void mma_bf16(float* d, const uint32_t* a, const uint32_t* b) {
    asm volatile(
        "mma.sync.aligned.m16n8k16.row.col.f32.bf16.bf16.f32 "
        "{%0,%1,%2,%3}, {%4,%5,%6,%7}, {%8,%9}, {%0,%1,%2,%3};"
        : "+f"(d[0]), "+f"(d[1]), "+f"(d[2]), "+f"(d[3])
        : "r"(a[0]), "r"(a[1]), "r"(a[2]), "r"(a[3]), "r"(b[0]), "r"(b[1]));
}
__device__ __forceinline__ float ex2f(float x) {
    float y;
    asm("ex2.approx.ftz.f32 %0, %1;" : "=f"(y) : "f"(x));
    return y;
}
__device__ __forceinline__ void split_pack(uint32_t& hi, uint32_t& lo, float a, float b) {
    __nv_bfloat162 h2 = __floats2bfloat162_rn(a, b);
    float2 hf = __bfloat1622float2(h2);
    __nv_bfloat162 l2 = __floats2bfloat162_rn(a - hf.x, b - hf.y);
    hi = *reinterpret_cast<uint32_t*>(&h2);
    lo = *reinterpret_cast<uint32_t*>(&l2);
}

// ---------------------------------------------------------------------------
// Conversion kernels
// ---------------------------------------------------------------------------
__global__ void __launch_bounds__(256)
convert_x_kernel(const float* __restrict__ x)
{
    size_t i4 = ((size_t)blockIdx.x * 256 + threadIdx.x) * 4;
    float4 v = *(const float4*)(x + i4);
    float vv[4] = {v.x, v.y, v.z, v.w};
    #pragma unroll
    for (int j = 0; j < 4; j++) {
        __nv_bfloat16 h = __float2bfloat16(vv[j]);
        g_xh[i4 + j] = h;
        g_xl[i4 + j] = __float2bfloat16(vv[j] - __bfloat162float(h));
    }
}

__global__ void __launch_bounds__(256)
convert_w_kernel(const float* __restrict__ Wq, const float* __restrict__ Wk,
                 const float* __restrict__ Wv, const float* __restrict__ Wp)
{
    __shared__ float tile[32][33];
    const int z = blockIdx.z;
    const float* W = (z == 0) ? Wq : (z == 1) ? Wk : (z == 2) ? Wv : Wp;
    const int n0 = blockIdx.x * 32, k0 = blockIdx.y * 32;
    const int tx = threadIdx.x & 31, ty = threadIdx.x >> 5;

    #pragma unroll
    for (int i = 0; i < 4; i++)
        tile[ty + i * 8][tx] = W[(size_t)(k0 + ty + i * 8) * C + n0 + tx];
    __syncthreads();

    __nv_bfloat16* wh = g_wh + (size_t)z * C * C;
    __nv_bfloat16* wl = g_wl + (size_t)z * C * C;
    #pragma unroll
    for (int i = 0; i < 4; i++) {
        const int n = n0 + ty + i * 8;
        const int k = k0 + tx;
        float v = tile[tx][ty + i * 8];
        __nv_bfloat16 h = __float2bfloat16(v);
        wh[(size_t)n * C + k] = h;
        wl[(size_t)n * C + k] = __float2bfloat16(v - __bfloat162float(h));
    }
}

// ---------------------------------------------------------------------------
// mma.sync split-bf16 GEMM, 128x128 CTA tile, 256 threads, 2 CTAs/SM.
// MODE 0: qkv -> split bf16 [B,H,T,D] (q pre-scaled by log2e/sqrt(D)).
// MODE 1: proj -> fp32 d_out.
// ---------------------------------------------------------------------------
constexpr int APITCHB = 80;
constexpr int MAT_B   = 128 * APITCHB;
constexpr int STAGE_B = 4 * MAT_B;
constexpr int GE_SMEM = 2 * STAGE_B;   // 81920

template<int MODE>
__global__ void __launch_bounds__(256, 2)
gemm_mma_kernel(const float* __restrict__ bias0, const float* __restrict__ bias1,
                const float* __restrict__ bias2, float* __restrict__ outp)
{
    extern __shared__ char smem[];
    const uint32_t sb = smem_to_u32(smem);
    const int tid  = threadIdx.x;
    const int wid  = tid >> 5;
    const int lane = tid & 31;
    const int warp_m = (wid & 1) * 64;
    const int warp_n = (wid >> 1) * 32;

    const int z = (MODE == 0) ? blockIdx.z : 3;
    const __nv_bfloat16* Ah = (MODE == 0) ? g_xh : g_yh;
    const __nv_bfloat16* Al = (MODE == 0) ? g_xl : g_yl;
    const __nv_bfloat16* Bh = g_wh + (size_t)z * C * C;
    const __nv_bfloat16* Bl = g_wl + (size_t)z * C * C;
    const float* bias = (MODE == 1) ? bias0 : (z == 0) ? bias0 : (z == 1) ? bias1 : bias2;
    __nv_bfloat16* outh = (z == 0) ? g_qh : (z == 1) ? g_kh : g_vh;
    __nv_bfloat16* outl = (z == 0) ? g_ql : (z == 1) ? g_kl : g_vl;
    // q pre-scaled by (1/sqrt(D)) * log2(e) so softmax runs in base 2
    const float oscale = (MODE == 0 && z == 0) ? 0.1803368801111244f : 1.0f;

    const int brow = blockIdx.y * 128;
    const int bcol = blockIdx.x * 128;

    uint32_t soff[2];
    size_t goffA[2], goffB[2];
    #pragma unroll
    for (int i = 0; i < 2; i++) {
        const int chunk = tid + i * 256;
        const int row = chunk >> 2;
        const int cc  = chunk & 3;
        soff[i]  = (uint32_t)(row * APITCHB + cc * 16);
        goffA[i] = (size_t)(brow + row) * C + cc * 8;
        goffB[i] = (size_t)(bcol + row) * C + cc * 8;
    }

    auto issue = [&](int s) {
        const int k0 = s * 32;
        const uint32_t base = sb + (uint32_t)(s & 1) * STAGE_B;
        #pragma unroll
        for (int i = 0; i < 2; i++) {
            cp_async16(base +             soff[i], Ah + goffA[i] + k0);
            cp_async16(base + MAT_B     + soff[i], Al + goffA[i] + k0);
            cp_async16(base + 2 * MAT_B + soff[i], Bh + goffB[i] + k0);
            cp_async16(base + 3 * MAT_B + soff[i], Bl + goffB[i] + k0);
        }
        CP_COMMIT();
    };

    float acc[4][4][4] = {};

    const int a_row  = warp_m + (lane & 15);
    const uint32_t a_half = (uint32_t)(lane >> 4) * 16;
    const int tt = lane >> 3;
    const int b_row  = warp_n + (tt >> 1) * 8 + (lane & 7);
    const uint32_t b_half = (uint32_t)(tt & 1) * 16;

    constexpr int NS = C / 32;
    issue(0);

    for (int s = 0; s < NS; s++) {
        if (s + 1 < NS) { issue(s + 1); CP_WAIT(1); }
        else            { CP_WAIT(0); }
        __syncthreads();

        const uint32_t base = sb + (uint32_t)(s & 1) * STAGE_B;
        #pragma unroll
        for (int ks = 0; ks < 2; ks++) {
            const uint32_t kb = (uint32_t)ks * 32;

            uint32_t ah[4][4], al[4][4];
            #pragma unroll
            for (int mt = 0; mt < 4; mt++) {
                const uint32_t ao = (uint32_t)((a_row + mt * 16) * APITCHB) + kb + a_half;
                ldsm_x4(ah[mt][0], ah[mt][1], ah[mt][2], ah[mt][3], base + ao);
                ldsm_x4(al[mt][0], al[mt][1], al[mt][2], al[mt][3], base + MAT_B + ao);
            }
            uint32_t bh[4][2], bl[4][2];
            #pragma unroll
            for (int np = 0; np < 2; np++) {
                const uint32_t bo = (uint32_t)((b_row + np * 16) * APITCHB) + kb + b_half;
                uint32_t r0, r1, r2, r3;
                ldsm_x4(r0, r1, r2, r3, base + 2 * MAT_B + bo);
                bh[np * 2][0] = r0; bh[np * 2][1] = r1;
                bh[np * 2 + 1][0] = r2; bh[np * 2 + 1][1] = r3;
                ldsm_x4(r0, r1, r2, r3, base + 3 * MAT_B + bo);
                bl[np * 2][0] = r0; bl[np * 2][1] = r1;
                bl[np * 2 + 1][0] = r2; bl[np * 2 + 1][1] = r3;
            }
            #pragma unroll
            for (int mt = 0; mt < 4; mt++)
                #pragma unroll
                for (int nt = 0; nt < 4; nt++) {
                    mma_bf16(acc[mt][nt], ah[mt], bh[nt]);
                    mma_bf16(acc[mt][nt], ah[mt], bl[nt]);
                    mma_bf16(acc[mt][nt], al[mt], bh[nt]);
                }
        }
        __syncthreads();
    }

    #pragma unroll
    for (int nt = 0; nt < 4; nt++) {
        const int n = bcol + warp_n + nt * 8 + (lane & 3) * 2;
        const float bn0 = __ldg(bias + n);
        const float bn1 = __ldg(bias + n + 1);
        #pragma unroll
        for (int mt = 0; mt < 4; mt++) {
            #pragma unroll
            for (int half = 0; half < 2; half++) {
                const int m = brow + warp_m + mt * 16 + (lane >> 2) + half * 8;
                const float v0 = (acc[mt][nt][half * 2 + 0] + bn0) * oscale;
                const float v1 = (acc[mt][nt][half * 2 + 1] + bn1) * oscale;
                if (MODE == 1) {
                    *(float2*)&outp[(size_t)m * C + n] = make_float2(v0, v1);
                } else {
                    const int bi = m >> 11, t = m & (T - 1);
                    const int hh = n >> 6, d = n & (D - 1);
                    const size_t idx = (((size_t)(bi * H + hh)) * T + t) * D + d;
                    uint32_t hi, lo;
                    split_pack(hi, lo, v0, v1);
                    *reinterpret_cast<uint32_t*>(&outh[idx]) = hi;
                    *reinterpret_cast<uint32_t*>(&outl[idx]) = lo;
                }
            }
        }
    }
}

// ---------------------------------------------------------------------------
// Tensor-core flash attention (causal), split-bf16 3-term MMA, base-2 softmax
// via explicit ex2.approx. CTA: 128 q-rows, 8 warps x 16 rows. K-tiles of 64.
// ---------------------------------------------------------------------------
constexpr int QPITCH  = 144;
constexpr int QMAT    = 128 * QPITCH;     // 18432
constexpr int KVMAT   = 64 * QPITCH;      // 9216
constexpr int KVSTAGE = 4 * KVMAT;        // 36864
constexpr int FA_SMEM = 2 * QMAT + 2 * KVSTAGE;  // 110592

__global__ void __launch_bounds__(256, 2)
flash_mma_kernel()
{
    extern __shared__ char smem[];
    const uint32_t sb = smem_to_u32(smem);
    const int tid  = threadIdx.x;
    const int wid  = tid >> 5;
    const int lane = tid & 31;
    const int gq   = lane >> 2;
    const int cq   = lane & 3;

    const int bh = blockIdx.y;
    const int qi = gridDim.x - 1 - blockIdx.x;     // heavy CTAs first
    const int qt = qi * 128;
    const size_t hoff = (size_t)bh * T * D;

    const __nv_bfloat16* kv_src[4] = {g_kh + hoff, g_kl + hoff, g_vh + hoff, g_vl + hoff};

    // issue Q (group), then KV stage 0
    {
        #pragma unroll
        for (int i = 0; i < 8; i++) {
            const int id = tid + i * 256;
            const int mat = id >> 10;
            const int cid = id & 1023;
            const int row = cid >> 3, cc = cid & 7;
            const __nv_bfloat16* src =
                (mat ? g_ql : g_qh) + hoff + (size_t)(qt + row) * D + cc * 8;
            cp_async16(sb + (uint32_t)(mat * QMAT + row * QPITCH + cc * 16), src);
        }
        CP_COMMIT();
    }
    auto issueKV = [&](int s_) {
        const int kt_ = s_ * 64;
        const uint32_t base = sb + 2 * QMAT + (uint32_t)(s_ & 1) * KVSTAGE;
        #pragma unroll
        for (int i = 0; i < 8; i++) {
            const int id = tid + i * 256;
            const int mat = id >> 9;
            const int cid = id & 511;
            const int row = cid >> 3, cc = cid & 7;
            cp_async16(base + (uint32_t)(mat * KVMAT + row * QPITCH + cc * 16),
                       kv_src[mat] + (size_t)(kt_ + row) * D + cc * 8);
        }
        CP_COMMIT();
    };
    issueKV(0);
    CP_WAIT(1);          // Q group done
    __syncthreads();

    // Q hi fragments resident; lo fragments reloaded per tile (register lean)
    const int qrow  = wid * 16 + (lane & 7) + ((lane >> 3) & 1) * 8;
    const int qcolb = (lane >> 4) * 8;
    uint32_t qfh[4][4];
    #pragma unroll
    for (int t = 0; t < 4; t++) {
        const uint32_t addr = sb + (uint32_t)(qrow * QPITCH + (t * 16 + qcolb) * 2);
        ldsm_x4(qfh[t][0], qfh[t][1], qfh[t][2], qfh[t][3], addr);
    }

    float oacc[8][4] = {};
    float m0 = -1e30f, m1 = -1e30f, l0 = 0.f, l1 = 0.f;
    const int qw0 = qt + wid * 16;
    const int ns = (qt >> 6) + 2;

    for (int s = 0; s < ns; s++) {
        if (s + 1 < ns) { issueKV(s + 1); CP_WAIT(1); }
        else            { CP_WAIT(0); }
        __syncthreads();

        const int kt = s * 64;
        if (kt <= qw0 + 15) {
            const uint32_t kvb = sb + 2 * QMAT + (uint32_t)(s & 1) * KVSTAGE;

            // S = Q K^T (split 3-term), logits in log2 domain (q pre-scaled)
            float sacc[8][4] = {};
            {
                const int kro = (lane & 7) + (lane >> 4) * 8;
                const int kco = ((lane >> 3) & 1) * 8;
                #pragma unroll
                for (int t = 0; t < 4; t++) {
                    uint32_t qlt[4];
                    const uint32_t qaddr = sb + QMAT +
                        (uint32_t)(qrow * QPITCH + (t * 16 + qcolb) * 2);
                    ldsm_x4(qlt[0], qlt[1], qlt[2], qlt[3], qaddr);
                    #pragma unroll
                    for (int jp = 0; jp < 4; jp++) {
                        uint32_t kh_[4], kl_[4];
                        const uint32_t addr = kvb +
                            (uint32_t)((jp * 16 + kro) * QPITCH + (t * 16 + kco) * 2);
                        ldsm_x4(kh_[0], kh_[1], kh_[2], kh_[3], addr);
                        ldsm_x4(kl_[0], kl_[1], kl_[2], kl_[3], addr + KVMAT);
                        #pragma unroll
                        for (int half = 0; half < 2; half++) {
                            const int n = jp * 2 + half;
                            mma_bf16(sacc[n], qfh[t], &kh_[half * 2]);
                            mma_bf16(sacc[n], qfh[t], &kl_[half * 2]);
                            mma_bf16(sacc[n], qlt,    &kh_[half * 2]);
                        }
                    }
                }
            }

            // causal mask (diagonal tiles only)
            if (kt + 63 > qw0) {
                const int q0 = qw0 + gq, q1 = q0 + 8;
                #pragma unroll
                for (int n = 0; n < 8; n++) {
                    const int key = kt + n * 8 + cq * 2;
                    if (key     > q0) sacc[n][0] = -1e30f;
                    if (key + 1 > q0) sacc[n][1] = -1e30f;
                    if (key     > q1) sacc[n][2] = -1e30f;
                    if (key + 1 > q1) sacc[n][3] = -1e30f;
                }
            }

            // online softmax (base 2, explicit EX2)
            float tm0 = -1e30f, tm1 = -1e30f;
            #pragma unroll
            for (int n = 0; n < 8; n++) {
                tm0 = fmaxf(tm0, fmaxf(sacc[n][0], sacc[n][1]));
                tm1 = fmaxf(tm1, fmaxf(sacc[n][2], sacc[n][3]));
            }
            tm0 = fmaxf(tm0, __shfl_xor_sync(0xffffffffu, tm0, 1));
            tm0 = fmaxf(tm0, __shfl_xor_sync(0xffffffffu, tm0, 2));
            tm1 = fmaxf(tm1, __shfl_xor_sync(0xffffffffu, tm1, 1));
            tm1 = fmaxf(tm1, __shfl_xor_sync(0xffffffffu, tm1, 2));
            const float nm0 = fmaxf(m0, tm0), nm1 = fmaxf(m1, tm1);
            const float al0 = ex2f(m0 - nm0), al1 = ex2f(m1 - nm1);
            m0 = nm0; m1 = nm1;
            float s0 = 0.f, s1 = 0.f;
            #pragma unroll
            for (int n = 0; n < 8; n++) {
                sacc[n][0] = ex2f(sacc[n][0] - nm0); s0 += sacc[n][0];
                sacc[n][1] = ex2f(sacc[n][1] - nm0); s0 += sacc[n][1];
                sacc[n][2] = ex2f(sacc[n][2] - nm1); s1 += sacc[n][2];
                sacc[n][3] = ex2f(sacc[n][3] - nm1); s1 += sacc[n][3];
            }
            s0 += __shfl_xor_sync(0xffffffffu, s0, 1);
            s0 += __shfl_xor_sync(0xffffffffu, s0, 2);
            s1 += __shfl_xor_sync(0xffffffffu, s1, 1);
            s1 += __shfl_xor_sync(0xffffffffu, s1, 2);
            l0 = l0 * al0 + s0;
            l1 = l1 * al1 + s1;
            #pragma unroll
            for (int j = 0; j < 8; j++) {
                oacc[j][0] *= al0; oacc[j][1] *= al0;
                oacc[j][2] *= al1; oacc[j][3] *= al1;
            }

            // O += P V (split 3-term); P packed from accumulators
            {
                const int vro = (lane & 7) + ((lane >> 3) & 1) * 8;
                const int vco = (lane >> 4) * 8;
                #pragma unroll
                for (int t = 0; t < 4; t++) {
                    uint32_t pah[4], pal[4];
                    split_pack(pah[0], pal[0], sacc[2 * t][0],     sacc[2 * t][1]);
                    split_pack(pah[1], pal[1], sacc[2 * t][2],     sacc[2 * t][3]);
                    split_pack(pah[2], pal[2], sacc[2 * t + 1][0], sacc[2 * t + 1][1]);
                    split_pack(pah[3], pal[3], sacc[2 * t + 1][2], sacc[2 * t + 1][3]);
                    #pragma unroll
                    for (int jp = 0; jp < 4; jp++) {
                        uint32_t vh_[4], vl_[4];
                        const uint32_t addr = kvb + 2 * KVMAT +
                            (uint32_t)((t * 16 + vro) * QPITCH + (jp * 16 + vco) * 2);
                        ldsm_x4_t(vh_[0], vh_[1], vh_[2], vh_[3], addr);
                        ldsm_x4_t(vl_[0], vl_[1], vl_[2], vl_[3], addr + KVMAT);
                        #pragma unroll
                        for (int half = 0; half < 2; half++) {
                            const int j = jp * 2 + half;
                            mma_bf16(oacc[j], pah, &vh_[half * 2]);
                            mma_bf16(oacc[j], pah, &vl_[half * 2]);
                            mma_bf16(oacc[j], pal, &vh_[half * 2]);
                        }
                    }
                }
            }
        }
        __syncthreads();
    }

    // epilogue: y = O / l, split-bf16 into g_yh/g_yl at [b, t, h*D + d]
    const int b = bh >> 4, h = bh & (H - 1);
    const float i0 = 1.0f / l0, i1 = 1.0f / l1;
    const int r0a = qw0 + gq, r1a = r0a + 8;
    #pragma unroll
    for (int j = 0; j < 8; j++) {
        const int col = j * 8 + cq * 2;
        const size_t idx0 = ((size_t)(b * T + r0a)) * C + h * D + col;
        const size_t idx1 = ((size_t)(b * T + r1a)) * C + h * D + col;
        uint32_t hh, ll;
        split_pack(hh, ll, oacc[j][0] * i0, oacc[j][1] * i0);
        *reinterpret_cast<uint32_t*>(&g_yh[idx0]) = hh;
        *reinterpret_cast<uint32_t*>(&g_yl[idx0]) = ll;
        split_pack(hh, ll, oacc[j][2] * i1, oacc[j][3] * i1);
        *reinterpret_cast<uint32_t*>(&g_yh[idx1]) = hh;
        *reinterpret_cast<uint32_t*>(&g_yl[idx1]) = ll;
    }
}

// ---------------------------------------------------------------------------
// Launch
// ---------------------------------------------------------------------------
extern "C" void kernel_launch(void* const* d_in, const int* in_sizes, int n_in,
                              void* d_out, int out_size)
{
    const float* x  = (const float*)d_in[0];
    const float* Wk = (const float*)d_in[1];
    const float* bk = (const float*)d_in[2];
    const float* Wq = (const float*)d_in[3];
    const float* bq = (const float*)d_in[4];
    const float* Wv = (const float*)d_in[5];
    const float* bv = (const float*)d_in[6];
    const float* Wp = (const float*)d_in[7];
    const float* bp = (const float*)d_in[8];
    float* out = (float*)d_out;

    // 0) conversions
    convert_x_kernel<<<(M * C) / (256 * 4), 256>>>(x);
    convert_w_kernel<<<dim3(C / 32, C / 32, 4), 256>>>(Wq, Wk, Wv, Wp);

    // 1) QKV projections (mma.sync bf16 split, split-bf16 outputs)
    cudaFuncSetAttribute(gemm_mma_kernel<0>,
                         cudaFuncAttributeMaxDynamicSharedMemorySize, GE_SMEM);
    gemm_mma_kernel<0><<<dim3(C / 128, M / 128, 3), 256, GE_SMEM>>>(bq, bk, bv, nullptr);

    // 2) causal flash attention on tensor cores
    cudaFuncSetAttribute(flash_mma_kernel,
                         cudaFuncAttributeMaxDynamicSharedMemorySize, FA_SMEM);
    flash_mma_kernel<<<dim3(T / 128, Bb * H), 256, FA_SMEM>>>();

    // 3) output projection (mma.sync bf16 split)
    cudaFuncSetAttribute(gemm_mma_kernel<1>,
                         cudaFuncAttributeMaxDynamicSharedMemorySize, GE_SMEM);
    gemm_mma_kernel<1><<<dim3(C / 128, M / 128, 1), 256, GE_SMEM>>>(bp, nullptr, nullptr, out);
}

// round 17
// speedup vs baseline: 2.3995x; 1.3981x over previous
#include <cuda_runtime.h>
#include <cuda_fp16.h>
#include <cstdint>
#include <math.h>

// Problem constants
constexpr int Bb = 4;
constexpr int T  = 2048;
constexpr int C  = 1024;
constexpr int H  = 16;
constexpr int D  = 64;
constexpr int M  = Bb * T;   // 8192

// ---------------------------------------------------------------------------
// Device scratch (allocation-free rule). fp16 pipeline:
//   A-operands split (exact), B-operands single-rounded fp16.
// ---------------------------------------------------------------------------
__device__ __half g_qh[(size_t)Bb * H * T * D];
__device__ __half g_ql[(size_t)Bb * H * T * D];
__device__ __half g_k [(size_t)Bb * H * T * D];
__device__ __half g_v [(size_t)Bb * H * T * D];
__device__ __half g_xh[(size_t)M * C];
__device__ __half g_xl[(size_t)M * C];
__device__ __half g_yh[(size_t)M * C];
__device__ __half g_yl[(size_t)M * C];
// transposed weights [N][K], single fp16, order: q, k, v, p
__device__ __half g_w[(size_t)4 * C * C];

// ---------------------------------------------------------------------------
// Baseline-PTX helpers
// ---------------------------------------------------------------------------
__device__ __forceinline__ uint32_t smem_to_u32(const void* p) {
    uint32_t a;
    asm("{ .reg .u64 t; cvta.to.shared.u64 t, %1; cvt.u32.u64 %0, t; }"
        : "=r"(a) : "l"(p));
    return a;
}
__device__ __forceinline__ void cp_async16(uint32_t dst, const void* src) {
    asm volatile("cp.async.cg.shared.global [%0], [%1], 16;"
                 :: "r"(dst), "l"(src) : "memory");
}
#define CP_COMMIT() asm volatile("cp.async.commit_group;" ::: "memory")
#define CP_WAIT(n)  asm volatile("cp.async.wait_group %0;" :: "n"(n) : "memory")

__device__ __forceinline__ void ldsm_x4(uint32_t& r0, uint32_t& r1,
                                        uint32_t& r2, uint32_t& r3, uint32_t addr) {
    asm volatile("ldmatrix.sync.aligned.m8n8.x4.shared.b16 {%0,%1,%2,%3}, [%4];"
                 : "=r"(r0), "=r"(r1), "=r"(r2), "=r"(r3) : "r"(addr));
}
__device__ __forceinline__ void ldsm_x4_t(uint32_t& r0, uint32_t& r1,
                                          uint32_t& r2, uint32_t& r3, uint32_t addr) {
    asm volatile("ldmatrix.sync.aligned.m8n8.x4.trans.shared.b16 {%0,%1,%2,%3}, [%4];"
                 : "=r"(r0), "=r"(r1), "=r"(r2), "=r"(r3) : "r"(addr));
}
__device__ __forceinline__ void mma_f16(float* d, const uint32_t* a, const uint32_t* b) {
    asm volatile(
        "mma.sync.aligned.m16n8k16.row.col.f32.f16.f16.f32 "
        "{%0,%1,%2,%3}, {%4,%5,%6,%7}, {%8,%9}, {%0,%1,%2,%3};"
        : "+f"(d[0]), "+f"(d[1]), "+f"(d[2]), "+f"(d[3])
        : "r"(a[0]), "r"(a[1]), "r"(a[2]), "r"(a[3]), "r"(b[0]), "r"(b[1]));
}
__device__ __forceinline__ float ex2f(float x) {
    float y;
    asm("ex2.approx.ftz.f32 %0, %1;" : "=f"(y) : "f"(x));
    return y;
}
// exact split: (hi, lo) fp16 pair with hi+lo ~= value to 2^-21
__device__ __forceinline__ void split_pack(uint32_t& hi, uint32_t& lo, float a, float b) {
    __half2 h2 = __floats2half2_rn(a, b);
    float2 hf = __half22float2(h2);
    __half2 l2 = __floats2half2_rn(a - hf.x, b - hf.y);
    hi = *reinterpret_cast<uint32_t*>(&h2);
    lo = *reinterpret_cast<uint32_t*>(&l2);
}
__device__ __forceinline__ uint32_t pack_h2(float a, float b) {
    __half2 h2 = __floats2half2_rn(a, b);
    return *reinterpret_cast<uint32_t*>(&h2);
}

// ---------------------------------------------------------------------------
// Conversion kernels
// ---------------------------------------------------------------------------
__global__ void __launch_bounds__(256)
convert_x_kernel(const float* __restrict__ x)
{
    size_t i4 = ((size_t)blockIdx.x * 256 + threadIdx.x) * 4;
    float4 v = *(const float4*)(x + i4);
    float vv[4] = {v.x, v.y, v.z, v.w};
    #pragma unroll
    for (int j = 0; j < 4; j++) {
        __half h = __float2half_rn(vv[j]);
        g_xh[i4 + j] = h;
        g_xl[i4 + j] = __float2half_rn(vv[j] - __half2float(h));
    }
}

// transpose W[k][n] -> Wt[n][k], single fp16; z = 0..3 selects matrix
__global__ void __launch_bounds__(256)
convert_w_kernel(const float* __restrict__ Wq, const float* __restrict__ Wk,
                 const float* __restrict__ Wv, const float* __restrict__ Wp)
{
    __shared__ float tile[32][33];
    const int z = blockIdx.z;
    const float* W = (z == 0) ? Wq : (z == 1) ? Wk : (z == 2) ? Wv : Wp;
    const int n0 = blockIdx.x * 32, k0 = blockIdx.y * 32;
    const int tx = threadIdx.x & 31, ty = threadIdx.x >> 5;

    #pragma unroll
    for (int i = 0; i < 4; i++)
        tile[ty + i * 8][tx] = W[(size_t)(k0 + ty + i * 8) * C + n0 + tx];
    __syncthreads();

    __half* w = g_w + (size_t)z * C * C;
    #pragma unroll
    for (int i = 0; i < 4; i++) {
        const int n = n0 + ty + i * 8;
        const int k = k0 + tx;
        w[(size_t)n * C + k] = __float2half_rn(tile[tx][ty + i * 8]);
    }
}

// ---------------------------------------------------------------------------
// mma.sync fp16 A-split GEMM: out = (Ah+Al) @ W^T + bias, exact in rounded W.
// 128x128 CTA tile, 256 threads, 2 CTAs/SM, 2 MMAs per k-step.
// MODE 0: qkv -> q split fp16 (pre-scaled log2e/sqrt(D)), k/v single fp16.
// MODE 1: proj -> fp32 d_out.
// ---------------------------------------------------------------------------
constexpr int APITCHB = 80;
constexpr int MAT_B   = 128 * APITCHB;   // 10240
constexpr int STAGE_B = 3 * MAT_B;       // 30720 (Ah, Al, B)
constexpr int GE_SMEM = 2 * STAGE_B;     // 61440

template<int MODE>
__global__ void __launch_bounds__(256, 2)
gemm_mma_kernel(const float* __restrict__ bias0, const float* __restrict__ bias1,
                const float* __restrict__ bias2, float* __restrict__ outp)
{
    extern __shared__ char smem[];
    const uint32_t sb = smem_to_u32(smem);
    const int tid  = threadIdx.x;
    const int wid  = tid >> 5;
    const int lane = tid & 31;
    const int warp_m = (wid & 1) * 64;
    const int warp_n = (wid >> 1) * 32;

    const int z = (MODE == 0) ? blockIdx.z : 3;
    const __half* Ah = (MODE == 0) ? g_xh : g_yh;
    const __half* Al = (MODE == 0) ? g_xl : g_yl;
    const __half* Bw = g_w + (size_t)z * C * C;
    const float* bias = (MODE == 1) ? bias0 : (z == 0) ? bias0 : (z == 1) ? bias1 : bias2;
    // q pre-scaled by (1/sqrt(D)) * log2(e) so softmax runs in base 2
    const float oscale = (MODE == 0 && z == 0) ? 0.1803368801111244f : 1.0f;

    const int brow = blockIdx.y * 128;
    const int bcol = blockIdx.x * 128;

    uint32_t soff[2];
    size_t goffA[2], goffB[2];
    #pragma unroll
    for (int i = 0; i < 2; i++) {
        const int chunk = tid + i * 256;
        const int row = chunk >> 2;
        const int cc  = chunk & 3;
        soff[i]  = (uint32_t)(row * APITCHB + cc * 16);
        goffA[i] = (size_t)(brow + row) * C + cc * 8;
        goffB[i] = (size_t)(bcol + row) * C + cc * 8;
    }

    auto issue = [&](int s) {
        const int k0 = s * 32;
        const uint32_t base = sb + (uint32_t)(s & 1) * STAGE_B;
        #pragma unroll
        for (int i = 0; i < 2; i++) {
            cp_async16(base +             soff[i], Ah + goffA[i] + k0);
            cp_async16(base + MAT_B     + soff[i], Al + goffA[i] + k0);
            cp_async16(base + 2 * MAT_B + soff[i], Bw + goffB[i] + k0);
        }
        CP_COMMIT();
    };

    float acc[4][4][4] = {};

    const int a_row  = warp_m + (lane & 15);
    const uint32_t a_half = (uint32_t)(lane >> 4) * 16;
    const int tt = lane >> 3;
    const int b_row  = warp_n + (tt >> 1) * 8 + (lane & 7);
    const uint32_t b_half = (uint32_t)(tt & 1) * 16;

    constexpr int NS = C / 32;
    issue(0);

    for (int s = 0; s < NS; s++) {
        if (s + 1 < NS) { issue(s + 1); CP_WAIT(1); }
        else            { CP_WAIT(0); }
        __syncthreads();

        const uint32_t base = sb + (uint32_t)(s & 1) * STAGE_B;
        #pragma unroll
        for (int ks = 0; ks < 2; ks++) {
            const uint32_t kb = (uint32_t)ks * 32;

            uint32_t ah[4][4], al[4][4];
            #pragma unroll
            for (int mt = 0; mt < 4; mt++) {
                const uint32_t ao = (uint32_t)((a_row + mt * 16) * APITCHB) + kb + a_half;
                ldsm_x4(ah[mt][0], ah[mt][1], ah[mt][2], ah[mt][3], base + ao);
                ldsm_x4(al[mt][0], al[mt][1], al[mt][2], al[mt][3], base + MAT_B + ao);
            }
            uint32_t bh[4][2];
            #pragma unroll
            for (int np = 0; np < 2; np++) {
                const uint32_t bo = (uint32_t)((b_row + np * 16) * APITCHB) + kb + b_half;
                uint32_t r0, r1, r2, r3;
                ldsm_x4(r0, r1, r2, r3, base + 2 * MAT_B + bo);
                bh[np * 2][0] = r0; bh[np * 2][1] = r1;
                bh[np * 2 + 1][0] = r2; bh[np * 2 + 1][1] = r3;
            }
            #pragma unroll
            for (int mt = 0; mt < 4; mt++)
                #pragma unroll
                for (int nt = 0; nt < 4; nt++) {
                    mma_f16(acc[mt][nt], ah[mt], bh[nt]);
                    mma_f16(acc[mt][nt], al[mt], bh[nt]);
                }
        }
        __syncthreads();
    }

    #pragma unroll
    for (int nt = 0; nt < 4; nt++) {
        const int n = bcol + warp_n + nt * 8 + (lane & 3) * 2;
        const float bn0 = __ldg(bias + n);
        const float bn1 = __ldg(bias + n + 1);
        #pragma unroll
        for (int mt = 0; mt < 4; mt++) {
            #pragma unroll
            for (int half = 0; half < 2; half++) {
                const int m = brow + warp_m + mt * 16 + (lane >> 2) + half * 8;
                const float v0 = (acc[mt][nt][half * 2 + 0] + bn0) * oscale;
                const float v1 = (acc[mt][nt][half * 2 + 1] + bn1) * oscale;
                if (MODE == 1) {
                    *(float2*)&outp[(size_t)m * C + n] = make_float2(v0, v1);
                } else {
                    const int bi = m >> 11, t = m & (T - 1);
                    const int hh = n >> 6, d = n & (D - 1);
                    const size_t idx = (((size_t)(bi * H + hh)) * T + t) * D + d;
                    if (z == 0) {
                        uint32_t hi, lo;
                        split_pack(hi, lo, v0, v1);
                        *reinterpret_cast<uint32_t*>(&g_qh[idx]) = hi;
                        *reinterpret_cast<uint32_t*>(&g_ql[idx]) = lo;
                    } else if (z == 1) {
                        *reinterpret_cast<uint32_t*>(&g_k[idx]) = pack_h2(v0, v1);
                    } else {
                        *reinterpret_cast<uint32_t*>(&g_v[idx]) = pack_h2(v0, v1);
                    }
                }
            }
        }
    }
}

// ---------------------------------------------------------------------------
// Tensor-core flash attention (causal), fp16 A-split 2-term MMA, base-2
// softmax. CTA: 128 q-rows, 8 warps x 16 rows. K-tiles of 64, double-buffered.
// ---------------------------------------------------------------------------
constexpr int QPITCH  = 144;
constexpr int QMAT    = 128 * QPITCH;     // 18432
constexpr int KVMAT   = 64 * QPITCH;      // 9216
constexpr int KVSTAGE = 2 * KVMAT;        // 18432 (k, v single)
constexpr int FA_SMEM = 2 * QMAT + 2 * KVSTAGE;  // 73728

__global__ void __launch_bounds__(256, 2)
flash_mma_kernel()
{
    extern __shared__ char smem[];
    const uint32_t sb = smem_to_u32(smem);
    const int tid  = threadIdx.x;
    const int wid  = tid >> 5;
    const int lane = tid & 31;
    const int gq   = lane >> 2;
    const int cq   = lane & 3;

    const int bh = blockIdx.y;
    const int qi = gridDim.x - 1 - blockIdx.x;     // heavy CTAs first
    const int qt = qi * 128;
    const size_t hoff = (size_t)bh * T * D;

    const __half* kv_src[2] = {g_k + hoff, g_v + hoff};

    // issue Q (qh, ql), then KV stage 0
    {
        #pragma unroll
        for (int i = 0; i < 8; i++) {
            const int id = tid + i * 256;
            const int mat = id >> 10;
            const int cid = id & 1023;
            const int row = cid >> 3, cc = cid & 7;
            const __half* src =
                (mat ? g_ql : g_qh) + hoff + (size_t)(qt + row) * D + cc * 8;
            cp_async16(sb + (uint32_t)(mat * QMAT + row * QPITCH + cc * 16), src);
        }
        CP_COMMIT();
    }
    auto issueKV = [&](int s_) {
        const int kt_ = s_ * 64;
        const uint32_t base = sb + 2 * QMAT + (uint32_t)(s_ & 1) * KVSTAGE;
        #pragma unroll
        for (int i = 0; i < 4; i++) {
            const int id = tid + i * 256;
            const int mat = id >> 9;
            const int cid = id & 511;
            const int row = cid >> 3, cc = cid & 7;
            cp_async16(base + (uint32_t)(mat * KVMAT + row * QPITCH + cc * 16),
                       kv_src[mat] + (size_t)(kt_ + row) * D + cc * 8);
        }
        CP_COMMIT();
    };
    issueKV(0);
    CP_WAIT(1);          // Q group done
    __syncthreads();

    // Q hi fragments resident; lo fragments reloaded per tile (register lean)
    const int qrow  = wid * 16 + (lane & 7) + ((lane >> 3) & 1) * 8;
    const int qcolb = (lane >> 4) * 8;
    uint32_t qfh[4][4];
    #pragma unroll
    for (int t = 0; t < 4; t++) {
        const uint32_t addr = sb + (uint32_t)(qrow * QPITCH + (t * 16 + qcolb) * 2);
        ldsm_x4(qfh[t][0], qfh[t][1], qfh[t][2], qfh[t][3], addr);
    }

    float oacc[8][4] = {};
    float m0 = -1e30f, m1 = -1e30f, l0 = 0.f, l1 = 0.f;
    const int qw0 = qt + wid * 16;
    const int ns = (qt >> 6) + 2;

    for (int s = 0; s < ns; s++) {
        if (s + 1 < ns) { issueKV(s + 1); CP_WAIT(1); }
        else            { CP_WAIT(0); }
        __syncthreads();

        const int kt = s * 64;
        if (kt <= qw0 + 15) {
            const uint32_t kvb = sb + 2 * QMAT + (uint32_t)(s & 1) * KVSTAGE;

            // S = (qh + ql) K^T — exact in stored fp16 K; logits in log2 domain
            float sacc[8][4] = {};
            {
                const int kro = (lane & 7) + (lane >> 4) * 8;
                const int kco = ((lane >> 3) & 1) * 8;
                #pragma unroll
                for (int t = 0; t < 4; t++) {
                    uint32_t qlt[4];
                    const uint32_t qaddr = sb + QMAT +
                        (uint32_t)(qrow * QPITCH + (t * 16 + qcolb) * 2);
                    ldsm_x4(qlt[0], qlt[1], qlt[2], qlt[3], qaddr);
                    #pragma unroll
                    for (int jp = 0; jp < 4; jp++) {
                        uint32_t kh_[4];
                        const uint32_t addr = kvb +
                            (uint32_t)((jp * 16 + kro) * QPITCH + (t * 16 + kco) * 2);
                        ldsm_x4(kh_[0], kh_[1], kh_[2], kh_[3], addr);
                        #pragma unroll
                        for (int half = 0; half < 2; half++) {
                            const int n = jp * 2 + half;
                            mma_f16(sacc[n], qfh[t], &kh_[half * 2]);
                            mma_f16(sacc[n], qlt,    &kh_[half * 2]);
                        }
                    }
                }
            }

            // causal mask (diagonal tiles only)
            if (kt + 63 > qw0) {
                const int q0 = qw0 + gq, q1 = q0 + 8;
                #pragma unroll
                for (int n = 0; n < 8; n++) {
                    const int key = kt + n * 8 + cq * 2;
                    if (key     > q0) sacc[n][0] = -1e30f;
                    if (key + 1 > q0) sacc[n][1] = -1e30f;
                    if (key     > q1) sacc[n][2] = -1e30f;
                    if (key + 1 > q1) sacc[n][3] = -1e30f;
                }
            }

            // online softmax (base 2, explicit EX2)
            float tm0 = -1e30f, tm1 = -1e30f;
            #pragma unroll
            for (int n = 0; n < 8; n++) {
                tm0 = fmaxf(tm0, fmaxf(sacc[n][0], sacc[n][1]));
                tm1 = fmaxf(tm1, fmaxf(sacc[n][2], sacc[n][3]));
            }
            tm0 = fmaxf(tm0, __shfl_xor_sync(0xffffffffu, tm0, 1));
            tm0 = fmaxf(tm0, __shfl_xor_sync(0xffffffffu, tm0, 2));
            tm1 = fmaxf(tm1, __shfl_xor_sync(0xffffffffu, tm1, 1));
            tm1 = fmaxf(tm1, __shfl_xor_sync(0xffffffffu, tm1, 2));
            const float nm0 = fmaxf(m0, tm0), nm1 = fmaxf(m1, tm1);
            const float al0 = ex2f(m0 - nm0), al1 = ex2f(m1 - nm1);
            m0 = nm0; m1 = nm1;
            float s0 = 0.f, s1 = 0.f;
            #pragma unroll
            for (int n = 0; n < 8; n++) {
                sacc[n][0] = ex2f(sacc[n][0] - nm0); s0 += sacc[n][0];
                sacc[n][1] = ex2f(sacc[n][1] - nm0); s0 += sacc[n][1];
                sacc[n][2] = ex2f(sacc[n][2] - nm1); s1 += sacc[n][2];
                sacc[n][3] = ex2f(sacc[n][3] - nm1); s1 += sacc[n][3];
            }
            s0 += __shfl_xor_sync(0xffffffffu, s0, 1);
            s0 += __shfl_xor_sync(0xffffffffu, s0, 2);
            s1 += __shfl_xor_sync(0xffffffffu, s1, 1);
            s1 += __shfl_xor_sync(0xffffffffu, s1, 2);
            l0 = l0 * al0 + s0;
            l1 = l1 * al1 + s1;
            #pragma unroll
            for (int j = 0; j < 8; j++) {
                oacc[j][0] *= al0; oacc[j][1] *= al0;
                oacc[j][2] *= al1; oacc[j][3] *= al1;
            }

            // O += (ph + pl) V — exact in stored fp16 V; P split in registers
            {
                const int vro = (lane & 7) + ((lane >> 3) & 1) * 8;
                const int vco = (lane >> 4) * 8;
                #pragma unroll
                for (int t = 0; t < 4; t++) {
                    uint32_t pah[4], pal[4];
                    split_pack(pah[0], pal[0], sacc[2 * t][0],     sacc[2 * t][1]);
                    split_pack(pah[1], pal[1], sacc[2 * t][2],     sacc[2 * t][3]);
                    split_pack(pah[2], pal[2], sacc[2 * t + 1][0], sacc[2 * t + 1][1]);
                    split_pack(pah[3], pal[3], sacc[2 * t + 1][2], sacc[2 * t + 1][3]);
                    #pragma unroll
                    for (int jp = 0; jp < 4; jp++) {
                        uint32_t vh_[4];
                        const uint32_t addr = kvb + KVMAT +
                            (uint32_t)((t * 16 + vro) * QPITCH + (jp * 16 + vco) * 2);
                        ldsm_x4_t(vh_[0], vh_[1], vh_[2], vh_[3], addr);
                        #pragma unroll
                        for (int half = 0; half < 2; half++) {
                            const int j = jp * 2 + half;
                            mma_f16(oacc[j], pah, &vh_[half * 2]);
                            mma_f16(oacc[j], pal, &vh_[half * 2]);
                        }
                    }
                }
            }
        }
        __syncthreads();
    }

    // epilogue: y = O / l, split fp16 into g_yh/g_yl at [b, t, h*D + d]
    const int b = bh >> 4, h = bh & (H - 1);
    const float i0 = 1.0f / l0, i1 = 1.0f / l1;
    const int r0a = qw0 + gq, r1a = r0a + 8;
    #pragma unroll
    for (int j = 0; j < 8; j++) {
        const int col = j * 8 + cq * 2;
        const size_t idx0 = ((size_t)(b * T + r0a)) * C + h * D + col;
        const size_t idx1 = ((size_t)(b * T + r1a)) * C + h * D + col;
        uint32_t hh, ll;
        split_pack(hh, ll, oacc[j][0] * i0, oacc[j][1] * i0);
        *reinterpret_cast<uint32_t*>(&g_yh[idx0]) = hh;
        *reinterpret_cast<uint32_t*>(&g_yl[idx0]) = ll;
        split_pack(hh, ll, oacc[j][2] * i1, oacc[j][3] * i1);
        *reinterpret_cast<uint32_t*>(&g_yh[idx1]) = hh;
        *reinterpret_cast<uint32_t*>(&g_yl[idx1]) = ll;
    }
}

// ---------------------------------------------------------------------------
// Launch
// ---------------------------------------------------------------------------
extern "C" void kernel_launch(void* const* d_in, const int* in_sizes, int n_in,
                              void* d_out, int out_size)
{
    const float* x  = (const float*)d_in[0];
    const float* Wk = (const float*)d_in[1];
    const float* bk = (const float*)d_in[2];
    const float* Wq = (const float*)d_in[3];
    const float* bq = (const float*)d_in[4];
    const float* Wv = (const float*)d_in[5];
    const float* bv = (const float*)d_in[6];
    const float* Wp = (const float*)d_in[7];
    const float* bp = (const float*)d_in[8];
    float* out = (float*)d_out;

    // 0) conversions
    convert_x_kernel<<<(M * C) / (256 * 4), 256>>>(x);
    convert_w_kernel<<<dim3(C / 32, C / 32, 4), 256>>>(Wq, Wk, Wv, Wp);

    // 1) QKV projections (fp16 A-split, 2 MMAs/k-step)
    cudaFuncSetAttribute(gemm_mma_kernel<0>,
                         cudaFuncAttributeMaxDynamicSharedMemorySize, GE_SMEM);
    gemm_mma_kernel<0><<<dim3(C / 128, M / 128, 3), 256, GE_SMEM>>>(bq, bk, bv, nullptr);

    // 2) causal flash attention on tensor cores
    cudaFuncSetAttribute(flash_mma_kernel,
                         cudaFuncAttributeMaxDynamicSharedMemorySize, FA_SMEM);
    flash_mma_kernel<<<dim3(T / 128, Bb * H), 256, FA_SMEM>>>();

    // 3) output projection (fp16 A-split, 2 MMAs/k-step)
    cudaFuncSetAttribute(gemm_mma_kernel<1>,
                         cudaFuncAttributeMaxDynamicSharedMemorySize, GE_SMEM);
    gemm_mma_kernel<1><<<dim3(C / 128, M / 128, 1), 256, GE_SMEM>>>(bp, nullptr, nullptr, out);
}